// round 10
// baseline (speedup 1.0000x reference)
#include <cuda_runtime.h>

#define Bn 256
#define Bh 128                 // half batch
#define Sn 196
#define Dn 2048
#define Hn 512
#define KSPLIT 32
#define KCHUNK (Dn / KSPLIT)   // 64
#define BK 16
#define TM 64
#define TN 64
#define TSTR 68    // tile row stride (floats): 64 + 4, keeps 16B alignment

// Scratch (no cudaMalloc allowed)
__device__ __align__(16) float g_atth_part[KSPLIT * Bn * Hn];  // 16 MB partials
__device__ __align__(16) float g_atth[Bn * Hn];
__device__ float g_scores[Bn * Sn];

// Hardware tanh approximation (MUFU.TANH, 1 instr; validated rel_err 2.6e-6)
__device__ __forceinline__ float htanh(float x) {
    float y;
    asm("tanh.approx.f32 %0, %1;" : "=f"(y) : "f"(x));
    return y;
}

// ---------------------------------------------------------------------------
// Kernel 1: split-K GEMM partials over HALF the batch (rows mbase..mbase+127).
//   part[z][m][n] = sum_{k in chunk z} h[m,k] * W[n,k]
// 64x64 tile, BK=16, 256 threads, 4x4/thread, double-buffered smem (R8 body).
// Grid (8, 2, 32) = 512 blocks -> full machine for a half-batch GEMM.
// ---------------------------------------------------------------------------
__global__ __launch_bounds__(256) void k_h2att_sk(const float* __restrict__ A,
                                                  const float* __restrict__ W,
                                                  int mbase) {
    __shared__ __align__(16) float As[2][BK * TSTR];   // [stage][k][m]
    __shared__ __align__(16) float Bs[2][BK * TSTR];   // [stage][k][n]
    const int tid = threadIdx.x;
    const int tx = tid & 15;          // n-quad -> n = tx*4
    const int ty = tid >> 4;          // m-quad -> m = ty*4
    const int n0 = blockIdx.x * TN;
    const int m0 = mbase + blockIdx.y * TM;
    const int kbase = blockIdx.z * KCHUNK;

    const int fr = tid >> 2;          // 0..63 (fill row)
    const int fc = (tid & 3) * 4;     // 0,4,8,12 (fill k-offset)

    const float* aptr = &A[(m0 + fr) * Dn + kbase + fc];
    const float* bptr = &W[(n0 + fr) * Dn + kbase + fc];

    float acc[4][4] = {};

    {   // prologue: tile 0 -> stage 0
        float4 a4 = *(const float4*)aptr;
        float4 b4 = *(const float4*)bptr;
#pragma unroll
        for (int i = 0; i < 4; i++) {
            As[0][(fc + i) * TSTR + fr] = (&a4.x)[i];
            Bs[0][(fc + i) * TSTR + fr] = (&b4.x)[i];
        }
    }
    __syncthreads();

    int buf = 0;
#pragma unroll
    for (int kt = 0; kt < KCHUNK; kt += BK) {
        const bool has_next = (kt + BK) < KCHUNK;
        float4 a4, b4;
        if (has_next) {                    // LDG in flight through compute
            a4 = *(const float4*)(aptr + kt + BK);
            b4 = *(const float4*)(bptr + kt + BK);
        }

#pragma unroll
        for (int k = 0; k < BK; k++) {
            float4 a = *(const float4*)&As[buf][k * TSTR + ty * 4];
            float4 b = *(const float4*)&Bs[buf][k * TSTR + tx * 4];
            acc[0][0] += a.x * b.x; acc[0][1] += a.x * b.y;
            acc[0][2] += a.x * b.z; acc[0][3] += a.x * b.w;
            acc[1][0] += a.y * b.x; acc[1][1] += a.y * b.y;
            acc[1][2] += a.y * b.z; acc[1][3] += a.y * b.w;
            acc[2][0] += a.z * b.x; acc[2][1] += a.z * b.y;
            acc[2][2] += a.z * b.z; acc[2][3] += a.z * b.w;
            acc[3][0] += a.w * b.x; acc[3][1] += a.w * b.y;
            acc[3][2] += a.w * b.z; acc[3][3] += a.w * b.w;
        }

        if (has_next) {
            const int nb = buf ^ 1;
#pragma unroll
            for (int i = 0; i < 4; i++) {
                As[nb][(fc + i) * TSTR + fr] = (&a4.x)[i];
                Bs[nb][(fc + i) * TSTR + fr] = (&b4.x)[i];
            }
            __syncthreads();
            buf = nb;
        }
    }

    float* dst = g_atth_part + (size_t)blockIdx.z * (Bn * Hn);
#pragma unroll
    for (int i = 0; i < 4; i++) {
        float4 v = make_float4(acc[i][0], acc[i][1], acc[i][2], acc[i][3]);
        *(float4*)&dst[(m0 + ty * 4 + i) * Hn + n0 + tx * 4] = v;
    }
}

// ---------------------------------------------------------------------------
// Kernel 2: reduce the 32 split-K partials + bias for a half batch.
// 65536 elements, L2-resident. Grid 256 x 256.
// ---------------------------------------------------------------------------
__global__ __launch_bounds__(256) void k_reduce(const float* __restrict__ bias,
                                                int bbase) {
    const int idx = (bbase * Hn) + blockIdx.x * 256 + threadIdx.x;
    float acc = bias[idx & (Hn - 1)];
#pragma unroll
    for (int z = 0; z < KSPLIT; z++)
        acc += g_atth_part[z * (Bn * Hn) + idx];
    g_atth[idx] = acc;
}

// ---------------------------------------------------------------------------
// Kernel 3: raw scores for a half batch, 2-slot ILP + hardware tanh.
// Grid (128, 7), 448 threads.
// ---------------------------------------------------------------------------
__global__ __launch_bounds__(448) void k_scores(const float* __restrict__ p_att,
                                                const float* __restrict__ w_alpha,
                                                const float* __restrict__ b_alpha,
                                                int bbase) {
    __shared__ float ah[Hn];
    __shared__ float wa[Hn];

    const int b = bbase + blockIdx.x;
    const int sgrp = blockIdx.y;          // 0..6, 28 slots each
    const int tid = threadIdx.x;
    const int lane = tid & 31;
    const int warp = tid >> 5;            // 0..13

    for (int h = tid; h < Hn; h += 448) {
        ah[h] = g_atth[b * Hn + h];
        wa[h] = w_alpha[h];
    }
    __syncthreads();

    const float balpha = b_alpha[0];
    const float4* a4p = (const float4*)ah;
    const float4* w4p = (const float4*)wa;

    const int s0 = sgrp * 28 + warp * 2;
    const float4* pr0 = (const float4*)(p_att + ((long)b * Sn + s0) * Hn);
    const float4* pr1 = (const float4*)(p_att + ((long)b * Sn + s0 + 1) * Hn);

    float l0 = 0.0f, l1 = 0.0f;
#pragma unroll
    for (int i = 0; i < 4; i++) {
        const int h4 = i * 32 + lane;
        float4 pa = pr0[h4];
        float4 pb = pr1[h4];
        float4 a4 = a4p[h4];
        float4 w4 = w4p[h4];
        l0 += htanh(pa.x + a4.x) * w4.x;
        l1 += htanh(pb.x + a4.x) * w4.x;
        l0 += htanh(pa.y + a4.y) * w4.y;
        l1 += htanh(pb.y + a4.y) * w4.y;
        l0 += htanh(pa.z + a4.z) * w4.z;
        l1 += htanh(pb.z + a4.z) * w4.z;
        l0 += htanh(pa.w + a4.w) * w4.w;
        l1 += htanh(pb.w + a4.w) * w4.w;
    }
#pragma unroll
    for (int o = 16; o > 0; o >>= 1) {
        l0 += __shfl_xor_sync(0xffffffffu, l0, o);
        l1 += __shfl_xor_sync(0xffffffffu, l1, o);
    }
    if (lane == 0) {
        g_scores[b * Sn + s0]     = l0 + balpha;
        g_scores[b * Sn + s0 + 1] = l1 + balpha;
    }
}

// ---------------------------------------------------------------------------
// Kernel 4: fused masked-softmax prologue + weighted sum, half batch.
// Grid (4, 128) x 128 threads. w_i = e_i*m_i / sum_j(e_j*m_j).
// ---------------------------------------------------------------------------
__global__ __launch_bounds__(128) void k_attres(const float* __restrict__ att_feats,
                                                const float* __restrict__ mask,
                                                float* __restrict__ out,
                                                int bbase) {
    __shared__ float w[Sn];
    __shared__ float redm[4];
    __shared__ float reds[4];

    const int b = bbase + blockIdx.y;
    const int tid = threadIdx.x;
    const int lane = tid & 31;
    const int warp = tid >> 5;

    const float v0 = g_scores[b * Sn + tid];
    const float v1 = (tid + 128 < Sn) ? g_scores[b * Sn + tid + 128] : -3.402823e38f;

    float m = fmaxf(v0, v1);
#pragma unroll
    for (int o = 16; o > 0; o >>= 1)
        m = fmaxf(m, __shfl_xor_sync(0xffffffffu, m, o));
    if (lane == 0) redm[warp] = m;
    __syncthreads();
    m = fmaxf(fmaxf(redm[0], redm[1]), fmaxf(redm[2], redm[3]));

    float e0 = __expf(v0 - m) * mask[b * Sn + tid];
    float e1 = (tid + 128 < Sn) ? __expf(v1 - m) * mask[b * Sn + tid + 128] : 0.0f;
    float s = e0 + e1;
#pragma unroll
    for (int o = 16; o > 0; o >>= 1)
        s += __shfl_xor_sync(0xffffffffu, s, o);
    if (lane == 0) reds[warp] = s;
    __syncthreads();
    const float inv = 1.0f / (reds[0] + reds[1] + reds[2] + reds[3]);

    w[tid] = e0 * inv;
    if (tid + 128 < Sn) w[tid + 128] = e1 * inv;
    __syncthreads();

    const int d0 = blockIdx.x * 512 + tid * 4;
    const float* base = att_feats + (long)b * Sn * Dn + d0;

    float4 acc = make_float4(0.f, 0.f, 0.f, 0.f);
#pragma unroll 8
    for (int s2 = 0; s2 < Sn; s2++) {
        float4 f = *(const float4*)(base + (long)s2 * Dn);
        float ws = w[s2];
        acc.x += ws * f.x;
        acc.y += ws * f.y;
        acc.z += ws * f.z;
        acc.w += ws * f.w;
    }
    *(float4*)(out + (long)b * Dn + d0) = acc;
}

// ---------------------------------------------------------------------------
// Two-stream half-batch pipeline (fork-join, graph-capture-safe):
//   s0: gemmA -> reduceA -> scoresA -> attresA -> [wait eB] -> attresB
//   s1: [wait eA] gemmB -> reduceB -> scoresB -> record eB
// gemmB (compute) overlaps scoresA (DRAM); scoresB overlaps attresA.
// ---------------------------------------------------------------------------

extern "C" void kernel_launch(void* const* d_in, const int* in_sizes, int n_in,
                              void* d_out, int out_size) {
    const float* h         = (const float*)d_in[0];  // [B, D]
    const float* att_feats = (const float*)d_in[1];  // [B, S, D]
    const float* p_att     = (const float*)d_in[2];  // [B, S, H]
    const float* mask      = (const float*)d_in[3];  // [B, S]
    const float* W_h2att   = (const float*)d_in[4];  // [H, D]
    const float* b_h2att   = (const float*)d_in[5];  // [H]
    const float* w_alpha   = (const float*)d_in[6];  // [H]
    const float* b_alpha   = (const float*)d_in[7];  // scalar
    float* out = (float*)d_out;                      // [B, D]

    (void)in_sizes; (void)n_in; (void)out_size;

    cudaStream_t s1;
    cudaStreamCreateWithFlags(&s1, cudaStreamNonBlocking);
    cudaEvent_t eA, eB;
    cudaEventCreateWithFlags(&eA, cudaEventDisableTiming);
    cudaEventCreateWithFlags(&eB, cudaEventDisableTiming);

    const dim3 gG(Hn / TN, Bh / TM, KSPLIT);  // (8, 2, 32) = 512 blocks
    const dim3 gS(Bh, 7);                     // 896 blocks
    const dim3 gR((Bh * Hn) / 256);           // 256 blocks
    const dim3 gA(4, Bh);                     // 512 blocks

    // ---- half A on stream 0 (capture-origin) ----
    k_h2att_sk<<<gG, 256>>>(h, W_h2att, 0);
    cudaEventRecord(eA, 0);                   // fork point: gemmB waits on gemmA

    // ---- half B on stream 1 ----
    cudaStreamWaitEvent(s1, eA, 0);
    k_h2att_sk<<<gG, 256, 0, s1>>>(h, W_h2att, Bh);
    k_reduce<<<gR, 256, 0, s1>>>(b_h2att, Bh);
    k_scores<<<gS, 448, 0, s1>>>(p_att, w_alpha, b_alpha, Bh);
    cudaEventRecord(eB, s1);

    // ---- continue half A on stream 0 ----
    k_reduce<<<gR, 256>>>(b_h2att, 0);
    k_scores<<<gS, 448>>>(p_att, w_alpha, b_alpha, 0);
    k_attres<<<gA, 128>>>(att_feats, mask, out, 0);

    // ---- join: half-B attres on stream 0 after scoresB ----
    cudaStreamWaitEvent(0, eB, 0);
    k_attres<<<gA, 128>>>(att_feats, mask, out, Bh);
}

// round 11
// speedup vs baseline: 1.2693x; 1.2693x over previous
#include <cuda_runtime.h>

#define Bn 256
#define Sn 196
#define Dn 2048
#define Hn 512
#define KSPLIT 16
#define KCHUNK (Dn / KSPLIT)   // 128
#define BK 16
#define TM 64
#define TN 64
#define TSTR 68    // tile row stride (floats): 64 + 4, keeps 16B alignment

// Scratch (no cudaMalloc allowed)
__device__ __align__(16) float g_atth_part[KSPLIT * Bn * Hn];  // 8 MB partials
__device__ float g_scores[Bn * Sn];

// Hardware tanh approximation (MUFU.TANH, 1 instr; validated rel_err 2.6e-6)
__device__ __forceinline__ float htanh(float x) {
    float y;
    asm("tanh.approx.f32 %0, %1;" : "=f"(y) : "f"(x));
    return y;
}

// ---------------------------------------------------------------------------
// Kernel 1: split-K GEMM partials, double-buffered smem pipeline (R8 body,
// proven 21.4us). Tile 64x64, BK=16, 256 threads, 4x4/thread.
// Grid (8, 4, 16) = 512 blocks.
// ---------------------------------------------------------------------------
__global__ __launch_bounds__(256) void k_h2att_sk(const float* __restrict__ A,
                                                  const float* __restrict__ W) {
    __shared__ __align__(16) float As[2][BK * TSTR];   // [stage][k][m]
    __shared__ __align__(16) float Bs[2][BK * TSTR];   // [stage][k][n]
    const int tid = threadIdx.x;
    const int tx = tid & 15;          // n-quad -> n = tx*4
    const int ty = tid >> 4;          // m-quad -> m = ty*4
    const int n0 = blockIdx.x * TN;
    const int m0 = blockIdx.y * TM;
    const int kbase = blockIdx.z * KCHUNK;

    const int fr = tid >> 2;          // 0..63 (fill row)
    const int fc = (tid & 3) * 4;     // 0,4,8,12 (fill k-offset)

    const float* aptr = &A[(m0 + fr) * Dn + kbase + fc];
    const float* bptr = &W[(n0 + fr) * Dn + kbase + fc];

    float acc[4][4] = {};

    {   // prologue: tile 0 -> stage 0
        float4 a4 = *(const float4*)aptr;
        float4 b4 = *(const float4*)bptr;
#pragma unroll
        for (int i = 0; i < 4; i++) {
            As[0][(fc + i) * TSTR + fr] = (&a4.x)[i];
            Bs[0][(fc + i) * TSTR + fr] = (&b4.x)[i];
        }
    }
    __syncthreads();

    int buf = 0;
#pragma unroll
    for (int kt = 0; kt < KCHUNK; kt += BK) {
        const bool has_next = (kt + BK) < KCHUNK;
        float4 a4, b4;
        if (has_next) {                    // LDG in flight through compute
            a4 = *(const float4*)(aptr + kt + BK);
            b4 = *(const float4*)(bptr + kt + BK);
        }

#pragma unroll
        for (int k = 0; k < BK; k++) {
            float4 a = *(const float4*)&As[buf][k * TSTR + ty * 4];
            float4 b = *(const float4*)&Bs[buf][k * TSTR + tx * 4];
            acc[0][0] += a.x * b.x; acc[0][1] += a.x * b.y;
            acc[0][2] += a.x * b.z; acc[0][3] += a.x * b.w;
            acc[1][0] += a.y * b.x; acc[1][1] += a.y * b.y;
            acc[1][2] += a.y * b.z; acc[1][3] += a.y * b.w;
            acc[2][0] += a.z * b.x; acc[2][1] += a.z * b.y;
            acc[2][2] += a.z * b.z; acc[2][3] += a.z * b.w;
            acc[3][0] += a.w * b.x; acc[3][1] += a.w * b.y;
            acc[3][2] += a.w * b.z; acc[3][3] += a.w * b.w;
        }

        if (has_next) {
            const int nb = buf ^ 1;
#pragma unroll
            for (int i = 0; i < 4; i++) {
                As[nb][(fc + i) * TSTR + fr] = (&a4.x)[i];
                Bs[nb][(fc + i) * TSTR + fr] = (&b4.x)[i];
            }
            __syncthreads();
            buf = nb;
        }
    }

    float* dst = g_atth_part + (size_t)blockIdx.z * (Bn * Hn);
#pragma unroll
    for (int i = 0; i < 4; i++) {
        float4 v = make_float4(acc[i][0], acc[i][1], acc[i][2], acc[i][3]);
        *(float4*)&dst[(m0 + ty * 4 + i) * Hn + n0 + tx * 4] = v;
    }
}

// ---------------------------------------------------------------------------
// Kernel 2: raw scores, 2-slot ILP + hardware tanh + register-pipelined
// p_att loads (prefetch iter i+1 while computing iter i).
// Grid (B, 7), 448 threads. att_h assembled from 16 partials + bias (L2).
// ---------------------------------------------------------------------------
__global__ __launch_bounds__(448) void k_scores(const float* __restrict__ p_att,
                                                const float* __restrict__ w_alpha,
                                                const float* __restrict__ bias,
                                                const float* __restrict__ b_alpha) {
    __shared__ float ah[Hn];
    __shared__ float wa[Hn];

    const int b = blockIdx.x;
    const int sgrp = blockIdx.y;          // 0..6, 28 slots each
    const int tid = threadIdx.x;
    const int lane = tid & 31;
    const int warp = tid >> 5;            // 0..13

    for (int h = tid; h < Hn; h += 448) {
        float acc = bias[h];
#pragma unroll
        for (int z = 0; z < KSPLIT; z++)
            acc += g_atth_part[z * (Bn * Hn) + b * Hn + h];
        ah[h] = acc;
        wa[h] = w_alpha[h];
    }
    __syncthreads();

    const float balpha = b_alpha[0];
    const float4* a4p = (const float4*)ah;
    const float4* w4p = (const float4*)wa;

    const int s0 = sgrp * 28 + warp * 2;
    const float4* pr0 = (const float4*)(p_att + ((long)b * Sn + s0) * Hn);
    const float4* pr1 = (const float4*)(p_att + ((long)b * Sn + s0 + 1) * Hn);

    float l0 = 0.0f, l1 = 0.0f;

    // register pipeline: prefetch next iteration's global loads
    float4 pa = pr0[lane];
    float4 pb = pr1[lane];
#pragma unroll
    for (int i = 0; i < 4; i++) {
        float4 pa_n, pb_n;
        if (i < 3) {
            const int h4n = (i + 1) * 32 + lane;
            pa_n = pr0[h4n];               // LDG in flight through the
            pb_n = pr1[h4n];               // tanh/FMA chain below
        }
        const int h4 = i * 32 + lane;
        float4 a4 = a4p[h4];
        float4 w4 = w4p[h4];
        l0 += htanh(pa.x + a4.x) * w4.x;
        l1 += htanh(pb.x + a4.x) * w4.x;
        l0 += htanh(pa.y + a4.y) * w4.y;
        l1 += htanh(pb.y + a4.y) * w4.y;
        l0 += htanh(pa.z + a4.z) * w4.z;
        l1 += htanh(pb.z + a4.z) * w4.z;
        l0 += htanh(pa.w + a4.w) * w4.w;
        l1 += htanh(pb.w + a4.w) * w4.w;
        if (i < 3) { pa = pa_n; pb = pb_n; }
    }
#pragma unroll
    for (int o = 16; o > 0; o >>= 1) {
        l0 += __shfl_xor_sync(0xffffffffu, l0, o);
        l1 += __shfl_xor_sync(0xffffffffu, l1, o);
    }
    if (lane == 0) {
        g_scores[b * Sn + s0]     = l0 + balpha;
        g_scores[b * Sn + s0 + 1] = l1 + balpha;
    }
}

// ---------------------------------------------------------------------------
// Kernel 3: fused masked-softmax prologue + weighted sum.
// Grid (4, B) x 128 threads. w_i = e_i*m_i / sum_j(e_j*m_j).
// ---------------------------------------------------------------------------
__global__ __launch_bounds__(128) void k_attres(const float* __restrict__ att_feats,
                                                const float* __restrict__ mask,
                                                float* __restrict__ out) {
    __shared__ float w[Sn];
    __shared__ float redm[4];
    __shared__ float reds[4];

    const int b = blockIdx.y;
    const int tid = threadIdx.x;
    const int lane = tid & 31;
    const int warp = tid >> 5;

    const float v0 = g_scores[b * Sn + tid];
    const float v1 = (tid + 128 < Sn) ? g_scores[b * Sn + tid + 128] : -3.402823e38f;

    float m = fmaxf(v0, v1);
#pragma unroll
    for (int o = 16; o > 0; o >>= 1)
        m = fmaxf(m, __shfl_xor_sync(0xffffffffu, m, o));
    if (lane == 0) redm[warp] = m;
    __syncthreads();
    m = fmaxf(fmaxf(redm[0], redm[1]), fmaxf(redm[2], redm[3]));

    float e0 = __expf(v0 - m) * mask[b * Sn + tid];
    float e1 = (tid + 128 < Sn) ? __expf(v1 - m) * mask[b * Sn + tid + 128] : 0.0f;
    float s = e0 + e1;
#pragma unroll
    for (int o = 16; o > 0; o >>= 1)
        s += __shfl_xor_sync(0xffffffffu, s, o);
    if (lane == 0) reds[warp] = s;
    __syncthreads();
    const float inv = 1.0f / (reds[0] + reds[1] + reds[2] + reds[3]);

    w[tid] = e0 * inv;
    if (tid + 128 < Sn) w[tid + 128] = e1 * inv;
    __syncthreads();

    const int d0 = blockIdx.x * 512 + tid * 4;
    const float* base = att_feats + (long)b * Sn * Dn + d0;

    float4 acc = make_float4(0.f, 0.f, 0.f, 0.f);
#pragma unroll 8
    for (int s2 = 0; s2 < Sn; s2++) {
        float4 f = *(const float4*)(base + (long)s2 * Dn);
        float ws = w[s2];
        acc.x += ws * f.x;
        acc.y += ws * f.y;
        acc.z += ws * f.z;
        acc.w += ws * f.w;
    }
    *(float4*)(out + (long)b * Dn + d0) = acc;
}

// ---------------------------------------------------------------------------

extern "C" void kernel_launch(void* const* d_in, const int* in_sizes, int n_in,
                              void* d_out, int out_size) {
    const float* h         = (const float*)d_in[0];  // [B, D]
    const float* att_feats = (const float*)d_in[1];  // [B, S, D]
    const float* p_att     = (const float*)d_in[2];  // [B, S, H]
    const float* mask      = (const float*)d_in[3];  // [B, S]
    const float* W_h2att   = (const float*)d_in[4];  // [H, D]
    const float* b_h2att   = (const float*)d_in[5];  // [H]
    const float* w_alpha   = (const float*)d_in[6];  // [H]
    const float* b_alpha   = (const float*)d_in[7];  // scalar
    float* out = (float*)d_out;                      // [B, D]

    (void)in_sizes; (void)n_in; (void)out_size;

    dim3 g1(Hn / TN, Bn / TM, KSPLIT);  // (8, 4, 16) = 512 blocks
    k_h2att_sk<<<g1, 256>>>(h, W_h2att);

    dim3 g2(Bn, 7);                     // 1792 blocks, 448 thr
    k_scores<<<g2, 448>>>(p_att, w_alpha, b_h2att, b_alpha);

    dim3 g3(4, Bn);                     // 1024 blocks
    k_attres<<<g3, 128>>>(att_feats, mask, out);
}

// round 13
// speedup vs baseline: 1.3049x; 1.0280x over previous
#include <cuda_runtime.h>
#include <cstdint>

#define Bn 256
#define Sn 196
#define Dn 2048
#define Hn 512
#define KSPLIT 16
#define KCHUNK (Dn / KSPLIT)   // 128
#define BKT 32                 // k-chunk per smem stage (GEMM)
#define ASTRIDE 36             // smem row stride (floats): 32 + 4

// Scratch (no cudaMalloc allowed)
__device__ __align__(16) float g_atth_part[KSPLIT * Bn * Hn];  // 8 MB partials
__device__ float g_scores[Bn * Sn];

// Hardware tanh approximation (MUFU.TANH, 1 instr; validated rel_err 2.6e-6)
__device__ __forceinline__ float htanh(float x) {
    float y;
    asm("tanh.approx.f32 %0, %1;" : "=f"(y) : "f"(x));
    return y;
}

// fp32 -> tf32 bits (round-to-nearest on 10-bit mantissa, low bits zero)
__device__ __forceinline__ uint32_t tf32_of(float x) {
    uint32_t u;
    asm("cvt.rna.tf32.f32 %0, %1;" : "=r"(u) : "f"(x));
    return u;
}

// D += A*B for one m16n8k8 tf32 atom
__device__ __forceinline__ void mma_tf32(float* c, const uint32_t* a, const uint32_t* b) {
    asm volatile(
        "mma.sync.aligned.m16n8k8.row.col.f32.tf32.tf32.f32 "
        "{%0,%1,%2,%3}, {%4,%5,%6,%7}, {%8,%9}, {%0,%1,%2,%3};"
        : "+f"(c[0]), "+f"(c[1]), "+f"(c[2]), "+f"(c[3])
        : "r"(a[0]), "r"(a[1]), "r"(a[2]), "r"(a[3]), "r"(b[0]), "r"(b[1]));
}

// ---------------------------------------------------------------------------
// Kernel 1: split-K GEMM partials on tensor cores, 3xTF32 compensation.
//   part[z][m][n] = sum_{k in chunk z} h[m,k] * W[n,k]
// Block 128 thr (4 warps, 2x2), tile 64m x 64n, BK=32.
// Each operand split x = hi + lo (tf32); D = hi*hi + lo*hi + hi*lo -> fp32-
// class accuracy (~2^-21 per-product). Grid (8, 4, 16) = 512 blocks.
// ---------------------------------------------------------------------------
__global__ __launch_bounds__(128) void k_h2att_sk(const float* __restrict__ A,
                                                  const float* __restrict__ W) {
    __shared__ __align__(16) uint32_t Ah[64 * ASTRIDE];  // [m][k] hi
    __shared__ __align__(16) uint32_t Al[64 * ASTRIDE];  // [m][k] lo
    __shared__ __align__(16) uint32_t Bh[64 * ASTRIDE];  // [n][k] hi
    __shared__ __align__(16) uint32_t Bl[64 * ASTRIDE];  // [n][k] lo

    const int tid = threadIdx.x;
    const int lane = tid & 31;
    const int warp = tid >> 5;            // 0..3
    const int g = lane >> 2;              // groupID 0..7
    const int tg = lane & 3;              // threadID_in_group 0..3
    const int wm = (warp >> 1) * 32;      // warp m-offset within tile
    const int wn = (warp & 1) * 32;       // warp n-offset within tile

    const int n0 = blockIdx.x * 64;
    const int m0 = blockIdx.y * 64;
    const int kbase = blockIdx.z * KCHUNK;

    const int fr = tid >> 1;              // fill row 0..63
    const int fk = (tid & 1) * 16;        // fill k-segment 0 or 16

    const float* arow = &A[(m0 + fr) * Dn + kbase];
    const float* brow = &W[(n0 + fr) * Dn + kbase];

    float c[2][4][4] = {};                // [m-atom][n-atom][frag]

    for (int kt = 0; kt < KCHUNK; kt += BKT) {
        __syncthreads();                  // previous compute done; smem reusable
        // ---- fill: split into tf32 hi/lo, store [row][k] ----
#pragma unroll
        for (int j = 0; j < 4; j++) {
            const int kk = fk + j * 4;
            float4 a4 = *(const float4*)(arow + kt + kk);
            float4 b4 = *(const float4*)(brow + kt + kk);
            uint4 ahi, alo, bhi, blo;
            ahi.x = tf32_of(a4.x); alo.x = tf32_of(a4.x - __uint_as_float(ahi.x));
            ahi.y = tf32_of(a4.y); alo.y = tf32_of(a4.y - __uint_as_float(ahi.y));
            ahi.z = tf32_of(a4.z); alo.z = tf32_of(a4.z - __uint_as_float(ahi.z));
            ahi.w = tf32_of(a4.w); alo.w = tf32_of(a4.w - __uint_as_float(ahi.w));
            bhi.x = tf32_of(b4.x); blo.x = tf32_of(b4.x - __uint_as_float(bhi.x));
            bhi.y = tf32_of(b4.y); blo.y = tf32_of(b4.y - __uint_as_float(bhi.y));
            bhi.z = tf32_of(b4.z); blo.z = tf32_of(b4.z - __uint_as_float(bhi.z));
            bhi.w = tf32_of(b4.w); blo.w = tf32_of(b4.w - __uint_as_float(bhi.w));
            *(uint4*)&Ah[fr * ASTRIDE + kk] = ahi;
            *(uint4*)&Al[fr * ASTRIDE + kk] = alo;
            *(uint4*)&Bh[fr * ASTRIDE + kk] = bhi;
            *(uint4*)&Bl[fr * ASTRIDE + kk] = blo;
        }
        __syncthreads();

        // ---- 4 k8-steps of mma ----
#pragma unroll
        for (int ks = 0; ks < 4; ks++) {
            const int kk = ks * 8;
            uint32_t ah[2][4], al[2][4], bh[4][2], bl[4][2];
#pragma unroll
            for (int am = 0; am < 2; am++) {
                const int r0 = (wm + am * 16 + g) * ASTRIDE + kk + tg;
                const int r8 = r0 + 8 * ASTRIDE;
                ah[am][0] = Ah[r0];     ah[am][1] = Ah[r8];
                ah[am][2] = Ah[r0 + 4]; ah[am][3] = Ah[r8 + 4];
                al[am][0] = Al[r0];     al[am][1] = Al[r8];
                al[am][2] = Al[r0 + 4]; al[am][3] = Al[r8 + 4];
            }
#pragma unroll
            for (int j = 0; j < 4; j++) {
                const int rb = (wn + j * 8 + g) * ASTRIDE + kk + tg;
                bh[j][0] = Bh[rb]; bh[j][1] = Bh[rb + 4];
                bl[j][0] = Bl[rb]; bl[j][1] = Bl[rb + 4];
            }
#pragma unroll
            for (int am = 0; am < 2; am++)
#pragma unroll
                for (int j = 0; j < 4; j++) {
                    mma_tf32(c[am][j], ah[am], bh[j]);   // hi*hi
                    mma_tf32(c[am][j], al[am], bh[j]);   // lo*hi
                    mma_tf32(c[am][j], ah[am], bl[j]);   // hi*lo
                }
        }
    }

    // ---- epilogue: c-fragment scatter to partials ----
    float* dst = g_atth_part + (size_t)blockIdx.z * (Bn * Hn);
#pragma unroll
    for (int am = 0; am < 2; am++) {
#pragma unroll
        for (int j = 0; j < 4; j++) {
            const int row = m0 + wm + am * 16 + g;
            const int col = n0 + wn + j * 8 + 2 * tg;
            *(float2*)&dst[row * Hn + col] =
                make_float2(c[am][j][0], c[am][j][1]);
            *(float2*)&dst[(row + 8) * Hn + col] =
                make_float2(c[am][j][2], c[am][j][3]);
        }
    }
}

// ---------------------------------------------------------------------------
// Kernel 2: raw scores, 2-slot ILP + hardware tanh (proven body).
// Grid (B, 7), 448 threads. att_h assembled from 16 partials + bias (L2).
// ---------------------------------------------------------------------------
__global__ __launch_bounds__(448) void k_scores(const float* __restrict__ p_att,
                                                const float* __restrict__ w_alpha,
                                                const float* __restrict__ bias,
                                                const float* __restrict__ b_alpha) {
    __shared__ float ah[Hn];
    __shared__ float wa[Hn];

    const int b = blockIdx.x;
    const int sgrp = blockIdx.y;          // 0..6, 28 slots each
    const int tid = threadIdx.x;
    const int lane = tid & 31;
    const int warp = tid >> 5;            // 0..13

    for (int h = tid; h < Hn; h += 448) {
        float acc = bias[h];
#pragma unroll
        for (int z = 0; z < KSPLIT; z++)
            acc += g_atth_part[z * (Bn * Hn) + b * Hn + h];
        ah[h] = acc;
        wa[h] = w_alpha[h];
    }
    __syncthreads();

    const float balpha = b_alpha[0];
    const float4* a4p = (const float4*)ah;
    const float4* w4p = (const float4*)wa;

    const int s0 = sgrp * 28 + warp * 2;
    const float4* pr0 = (const float4*)(p_att + ((long)b * Sn + s0) * Hn);
    const float4* pr1 = (const float4*)(p_att + ((long)b * Sn + s0 + 1) * Hn);

    float l0 = 0.0f, l1 = 0.0f;
#pragma unroll
    for (int i = 0; i < 4; i++) {
        const int h4 = i * 32 + lane;
        float4 pa = pr0[h4];
        float4 pb = pr1[h4];
        float4 a4 = a4p[h4];
        float4 w4 = w4p[h4];
        l0 += htanh(pa.x + a4.x) * w4.x;
        l1 += htanh(pb.x + a4.x) * w4.x;
        l0 += htanh(pa.y + a4.y) * w4.y;
        l1 += htanh(pb.y + a4.y) * w4.y;
        l0 += htanh(pa.z + a4.z) * w4.z;
        l1 += htanh(pb.z + a4.z) * w4.z;
        l0 += htanh(pa.w + a4.w) * w4.w;
        l1 += htanh(pb.w + a4.w) * w4.w;
    }
#pragma unroll
    for (int o = 16; o > 0; o >>= 1) {
        l0 += __shfl_xor_sync(0xffffffffu, l0, o);
        l1 += __shfl_xor_sync(0xffffffffu, l1, o);
    }
    if (lane == 0) {
        g_scores[b * Sn + s0]     = l0 + balpha;
        g_scores[b * Sn + s0 + 1] = l1 + balpha;
    }
}

// ---------------------------------------------------------------------------
// Kernel 3: fused masked-softmax prologue + weighted sum.
// Grid (4, B) x 128 threads. w_i = e_i*m_i / sum_j(e_j*m_j).
// ---------------------------------------------------------------------------
__global__ __launch_bounds__(128) void k_attres(const float* __restrict__ att_feats,
                                                const float* __restrict__ mask,
                                                float* __restrict__ out) {
    __shared__ float w[Sn];
    __shared__ float redm[4];
    __shared__ float reds[4];

    const int b = blockIdx.y;
    const int tid = threadIdx.x;
    const int lane = tid & 31;
    const int warp = tid >> 5;

    const float v0 = g_scores[b * Sn + tid];
    const float v1 = (tid + 128 < Sn) ? g_scores[b * Sn + tid + 128] : -3.402823e38f;

    float m = fmaxf(v0, v1);
#pragma unroll
    for (int o = 16; o > 0; o >>= 1)
        m = fmaxf(m, __shfl_xor_sync(0xffffffffu, m, o));
    if (lane == 0) redm[warp] = m;
    __syncthreads();
    m = fmaxf(fmaxf(redm[0], redm[1]), fmaxf(redm[2], redm[3]));

    float e0 = __expf(v0 - m) * mask[b * Sn + tid];
    float e1 = (tid + 128 < Sn) ? __expf(v1 - m) * mask[b * Sn + tid + 128] : 0.0f;
    float s = e0 + e1;
#pragma unroll
    for (int o = 16; o > 0; o >>= 1)
        s += __shfl_xor_sync(0xffffffffu, s, o);
    if (lane == 0) reds[warp] = s;
    __syncthreads();
    const float inv = 1.0f / (reds[0] + reds[1] + reds[2] + reds[3]);

    w[tid] = e0 * inv;
    if (tid + 128 < Sn) w[tid + 128] = e1 * inv;
    __syncthreads();

    const int d0 = blockIdx.x * 512 + tid * 4;
    const float* base = att_feats + (long)b * Sn * Dn + d0;

    float4 acc = make_float4(0.f, 0.f, 0.f, 0.f);
#pragma unroll 8
    for (int s2 = 0; s2 < Sn; s2++) {
        float4 f = *(const float4*)(base + (long)s2 * Dn);
        float ws = w[s2];
        acc.x += ws * f.x;
        acc.y += ws * f.y;
        acc.z += ws * f.z;
        acc.w += ws * f.w;
    }
    *(float4*)(out + (long)b * Dn + d0) = acc;
}

// ---------------------------------------------------------------------------

extern "C" void kernel_launch(void* const* d_in, const int* in_sizes, int n_in,
                              void* d_out, int out_size) {
    const float* h         = (const float*)d_in[0];  // [B, D]
    const float* att_feats = (const float*)d_in[1];  // [B, S, D]
    const float* p_att     = (const float*)d_in[2];  // [B, S, H]
    const float* mask      = (const float*)d_in[3];  // [B, S]
    const float* W_h2att   = (const float*)d_in[4];  // [H, D]
    const float* b_h2att   = (const float*)d_in[5];  // [H]
    const float* w_alpha   = (const float*)d_in[6];  // [H]
    const float* b_alpha   = (const float*)d_in[7];  // scalar
    float* out = (float*)d_out;                      // [B, D]

    (void)in_sizes; (void)n_in; (void)out_size;

    dim3 g1(Hn / 64, Bn / 64, KSPLIT);  // (8, 4, 16) = 512 blocks
    k_h2att_sk<<<g1, 128>>>(h, W_h2att);

    dim3 g2(Bn, 7);                     // 1792 blocks, 448 thr
    k_scores<<<g2, 448>>>(p_att, w_alpha, b_h2att, b_alpha);

    dim3 g3(4, Bn);                     // 1024 blocks
    k_attres<<<g3, 128>>>(att_feats, mask, out);
}